// round 10
// baseline (speedup 1.0000x reference)
#include <cuda_runtime.h>

// Kalman filter, simple-form update, COLUMN-SPLIT layout for 2x occupancy.
// B=4096, T=200, S=8, M=2.
// 16 threads per batch: thread (i = row, c = column-half) owns P[i][4c..4c+3].
// 2 batches per 32-thread warp/block, 2048 blocks (~13.8 warps/SM, 3.46/SMSP).
// Cross-half communication via __shfl_xor_sync(...,8); matmul operands (P_u, F)
// in per-batch SMEM with bank-disjoint layouts (F rows at stride 12).
//
// Per step:
//   hp  (partial over own cols) -> shfl-xor reduce -> full HP col i
//   S = HP H^T + R ; gain (w0i,w1i) ; P_u quarter-row -> SMEM
//   G[i][own cols] = F_row_i . Pu[:, own cols]   (column-slice LDS)
//   g exchange (4 shfl) ; P'[i][own cols] = G_row . F_rows(own k) + Q
// 3 syncwarps per step.

namespace {
constexpr int Bb  = 4096;
constexpr int Tt  = 200;
constexpr int WSF = 200;   // per-batch workspace stride (mod 32 == 8, 16B-aligned)
}

__global__ __launch_bounds__(32)
void kalman_kernel(const float* __restrict__ gy,      // [B,T,2]
                   const float* __restrict__ gF,      // [B,T,8,8]
                   const float* __restrict__ gH,      // [B,T,2,8]
                   const float* __restrict__ gQ,      // [8,8]
                   const float* __restrict__ gR,      // [2,2]
                   const float* __restrict__ gMean0,  // [B,8]
                   const float* __restrict__ gCov0,   // [8,8]
                   float* __restrict__ oMean,         // [B,T,8]
                   float* __restrict__ oCov)          // [B,T,8,8]
{
    __shared__ __align__(16) float sw[2 * WSF];
    const int lane = threadIdx.x;
    const int lb   = lane >> 4;          // batch within warp (0/1)
    const int t16  = lane & 15;
    const int i    = t16 & 7;            // state row
    const int c    = t16 >> 3;           // column half (0/1)
    const int cb   = c * 4;              // first owned column
    const int b    = blockIdx.x * 2 + lb;

    float* wsp   = sw + lb * WSF;
    float* sPU   = wsp;          // 64:  P_u, row stride 8
    float* sF    = wsp + 64;     // 96:  F, row stride 12 (bank stagger)
    float* sHP   = wsp + 160;    // 16:  HP interleaved (hp0,hp1) per column
    float* sMU   = wsp + 176;    //  8:  updated mean
    float* sMean = wsp + 184;    //  8:  predicted mean

    // Loop-invariant constants
    const float R00 = gR[0], R01 = gR[1], R10 = gR[2], R11 = gR[3];
    float Qr[4];
#pragma unroll
    for (int m = 0; m < 4; ++m) Qr[m] = gQ[i * 8 + cb + m];

    float* omb = oMean + (size_t)b * Tt * 8;
    float* ocb = oCov  + (size_t)b * Tt * 64;

    // ---- init: own quarter-row of P; t=0 outputs ----
    float pr[4];
    {
        const float4 p0 = *(const float4*)(gCov0 + i * 8 + cb);
        pr[0]=p0.x; pr[1]=p0.y; pr[2]=p0.z; pr[3]=p0.w;
        *(float4*)(ocb + i * 8 + cb) = p0;
    }
    if (c == 0) {
        const float m0 = gMean0[b * 8 + i];
        sMean[i] = m0;
        omb[i]   = m0;
    }

    const float* Fb = gF + (size_t)b * Tt * 64;
    const float* Hb = gH + (size_t)b * Tt * 16;
    const float* yb = gy + (size_t)b * Tt * 2;

    // ---- prefetch step 0 ----
    float4 fh = *(const float4*)(Fb + i * 8 + cb);   // own F quarter-row
    float4 h0 = *(const float4*)(Hb);
    float4 h1 = *(const float4*)(Hb + 4);
    float4 h2 = *(const float4*)(Hb + 8);
    float4 h3 = *(const float4*)(Hb + 12);
    float2 yv = *(const float2*)(yb);

    __syncwarp();

    for (int t = 0; t < Tt - 1; ++t) {
        const float frh[4] = {fh.x, fh.y, fh.z, fh.w};
        const float ha[8]  = {h0.x, h0.y, h0.z, h0.w, h1.x, h1.y, h1.z, h1.w};
        const float hc[8]  = {h2.x, h2.y, h2.z, h2.w, h3.x, h3.y, h3.z, h3.w};
        const float y0 = yv.x, y1 = yv.y;

        // prefetch next step
        {
            const float* Fn = Fb + (size_t)(t + 1) * 64;
            fh = *(const float4*)(Fn + i * 8 + cb);
            const float* Hn = Hb + (size_t)(t + 1) * 16;
            h0 = *(const float4*)(Hn);
            h1 = *(const float4*)(Hn + 4);
            h2 = *(const float4*)(Hn + 8);
            h3 = *(const float4*)(Hn + 12);
            yv = *(const float2*)(yb + (size_t)(t + 1) * 2);
        }

        // ---- phase 1: F quarter-row to SMEM; HP partial + shfl reduce ----
        *(float4*)(sF + i * 12 + cb) = make_float4(frh[0], frh[1], frh[2], frh[3]);
        // hp over own columns s = cb..cb+3 (P symmetric: P[s][i] = P[i][s])
        float hp0 = 0.f, hp1 = 0.f;
#pragma unroll
        for (int m = 0; m < 4; ++m) {
            hp0 += (c ? ha[4 + m] : ha[m]) * pr[m];
            hp1 += (c ? hc[4 + m] : hc[m]) * pr[m];
        }
        hp0 += __shfl_xor_sync(0xffffffffu, hp0, 8);
        hp1 += __shfl_xor_sync(0xffffffffu, hp1, 8);
        if (c == 0) *(float2*)(sHP + 2 * i) = make_float2(hp0, hp1);
        __syncwarp();  // sync A: sF, sHP visible

        // ---- phase 2: S, gain, P_u quarter-row, mean_u ----
        float HP0[8], HP1[8];
        {
            float4 v = *(const float4*)(sHP);
            HP0[0]=v.x; HP1[0]=v.y; HP0[1]=v.z; HP1[1]=v.w;
            v = *(const float4*)(sHP + 4);
            HP0[2]=v.x; HP1[2]=v.y; HP0[3]=v.z; HP1[3]=v.w;
            v = *(const float4*)(sHP + 8);
            HP0[4]=v.x; HP1[4]=v.y; HP0[5]=v.z; HP1[5]=v.w;
            v = *(const float4*)(sHP + 12);
            HP0[6]=v.x; HP1[6]=v.y; HP0[7]=v.z; HP1[7]=v.w;
        }
        float s00 = R00, s01 = R01, s10 = R10, s11 = R11;
#pragma unroll
        for (int k = 0; k < 8; ++k) {
            s00 += HP0[k] * ha[k];
            s01 += HP0[k] * hc[k];
            s10 += HP1[k] * ha[k];
            s11 += HP1[k] * hc[k];
        }
        const float inv = 1.0f / (s00 * s11 - s01 * s10);
        const float w0i = inv * ( s11 * hp0 - s01 * hp1);
        const float w1i = inv * (-s10 * hp0 + s00 * hp1);

        // P_u quarter-row: pu[m] = pr[m] - w0i*HP0[cb+m] - w1i*HP1[cb+m]
        float pu[4];
#pragma unroll
        for (int m = 0; m < 4; ++m) {
            const float a0 = c ? HP0[4 + m] : HP0[m];
            const float a1 = c ? HP1[4 + m] : HP1[m];
            pu[m] = pr[m] - w0i * a0 - w1i * a1;
        }
        *(float4*)(sPU + i * 8 + cb) = make_float4(pu[0], pu[1], pu[2], pu[3]);

        // other half of own F row (stored before sync A)
        const float4 fo4 = *(const float4*)(sF + i * 12 + (4 - cb));
        const float fo[4] = {fo4.x, fo4.y, fo4.z, fo4.w};
        // full F row i, in column order 0..7
        float frlo[4], frhi[4];
#pragma unroll
        for (int m = 0; m < 4; ++m) {
            frlo[m] = c ? fo[m]  : frh[m];
            frhi[m] = c ? frh[m] : fo[m];
        }

        // mean update (c == 0 lanes only)
        if (c == 0) {
            const float4 m0 = *(const float4*)(sMean);
            const float4 m1 = *(const float4*)(sMean + 4);
            float r0 = y0, r1 = y1;
            r0 -= ha[0]*m0.x + ha[1]*m0.y + ha[2]*m0.z + ha[3]*m0.w
                + ha[4]*m1.x + ha[5]*m1.y + ha[6]*m1.z + ha[7]*m1.w;
            r1 -= hc[0]*m0.x + hc[1]*m0.y + hc[2]*m0.z + hc[3]*m0.w
                + hc[4]*m1.x + hc[5]*m1.y + hc[6]*m1.z + hc[7]*m1.w;
            const float mni = sMean[i];
            sMU[i] = mni + w0i * r0 + w1i * r1;
        }
        __syncwarp();  // sync B: sPU, sMU visible; all sMean reads done

        // ---- phase 3: predict ----
        // G[i][cb+m] = sum_j F[i][j] * Pu[j][cb+m]  (column-slice loads)
        float g[4] = {0, 0, 0, 0};
#pragma unroll
        for (int j = 0; j < 8; ++j) {
            const float4 pj = *(const float4*)(sPU + j * 8 + cb);
            const float fj = (j < 4) ? frlo[j] : frhi[j - 4];
            g[0] += fj * pj.x; g[1] += fj * pj.y;
            g[2] += fj * pj.z; g[3] += fj * pj.w;
        }
        // exchange G halves with partner lane (i, 1-c)
        float rx[4];
#pragma unroll
        for (int m = 0; m < 4; ++m)
            rx[m] = __shfl_xor_sync(0xffffffffu, g[m], 8);

        // P'[i][k] for k = cb..cb+3:  g . F[k][own cols] + rx . F[k][other cols] + Q
        float pn[4];
#pragma unroll
        for (int kk = 0; kk < 4; ++kk) {
            const int k = cb + kk;
            const float4 q0 = *(const float4*)(sF + k * 12);      // F[k][0..3]
            const float4 q1 = *(const float4*)(sF + k * 12 + 4);  // F[k][4..7]
            const float4 qow = c ? q1 : q0;   // matches g (own cols)
            const float4 qot = c ? q0 : q1;   // matches rx
            pn[kk] = Qr[kk]
                   + g[0]*qow.x + g[1]*qow.y + g[2]*qow.z + g[3]*qow.w
                   + rx[0]*qot.x + rx[1]*qot.y + rx[2]*qot.z + rx[3]*qot.w;
        }
#pragma unroll
        for (int m = 0; m < 4; ++m) pr[m] = pn[m];

        // outputs
        *(float4*)(ocb + (size_t)(t + 1) * 64 + i * 8 + cb) =
            make_float4(pn[0], pn[1], pn[2], pn[3]);

        if (c == 0) {
            const float4 u0 = *(const float4*)(sMU);
            const float4 u1 = *(const float4*)(sMU + 4);
            const float mp =
                  frlo[0]*u0.x + frlo[1]*u0.y + frlo[2]*u0.z + frlo[3]*u0.w
                + frhi[0]*u1.x + frhi[1]*u1.y + frhi[2]*u1.z + frhi[3]*u1.w;
            sMean[i] = mp;                       // reads of old sMean ended before sync B
            omb[(size_t)(t + 1) * 8 + i] = mp;
        }
        __syncwarp();  // sync C: phase-3 reads done; sMean visible next iter
    }
}

extern "C" void kernel_launch(void* const* d_in, const int* in_sizes, int n_in,
                              void* d_out, int out_size)
{
    // metadata order: y, F, H, Q, R, init_mean, init_cov, n_step
    const float* gy     = (const float*)d_in[0];
    const float* gF     = (const float*)d_in[1];
    const float* gH     = (const float*)d_in[2];
    const float* gQ     = (const float*)d_in[3];
    const float* gR     = (const float*)d_in[4];
    const float* gMean0 = (const float*)d_in[5];
    const float* gCov0  = (const float*)d_in[6];
    (void)in_sizes; (void)n_in;

    float* oMean = (float*)d_out;                          // [B,T,8]
    float* oCov  = (float*)d_out + (size_t)Bb * Tt * 8;    // [B,T,8,8]
    (void)out_size;

    kalman_kernel<<<Bb / 2, 32>>>(gy, gF, gH, gQ, gR, gMean0, gCov0,
                                  oMean, oCov);
}

// round 11
// speedup vs baseline: 1.2387x; 1.2387x over previous
#include <cuda_runtime.h>

// Kalman filter, simple-form update, select-free column-split layout.
// B=4096, T=200, S=8, M=2.
// 16 threads/batch: lane (i = state row, c = column half) owns P[i][4c..4c+3].
// 2 batches per 32-thread warp, 2048 warps (~13.8/SM, 3.46/SMSP).
// All half-selection done via per-lane addresses (LDG/LDS offsets) and
// shfl_xor(8) partner exchanges -- zero SEL chains in the inner loop.
// Batch SMEM stride 208 (== 16 mod 32): every 4-address broadcast LDS is
// bank-disjoint across the (batch, half) groups.

namespace {
constexpr int Bb  = 4096;
constexpr int Tt  = 200;
constexpr int WSF = 208;   // per-batch workspace stride in floats
constexpr unsigned FULL = 0xffffffffu;
}

__global__ __launch_bounds__(32)
void kalman_kernel(const float* __restrict__ gy,      // [B,T,2]
                   const float* __restrict__ gF,      // [B,T,8,8]
                   const float* __restrict__ gH,      // [B,T,2,8]
                   const float* __restrict__ gQ,      // [8,8]
                   const float* __restrict__ gR,      // [2,2]
                   const float* __restrict__ gMean0,  // [B,8]
                   const float* __restrict__ gCov0,   // [8,8]
                   float* __restrict__ oMean,         // [B,T,8]
                   float* __restrict__ oCov)          // [B,T,8,8]
{
    __shared__ __align__(16) float sw[2 * WSF];
    const int lane = threadIdx.x;
    const int lb   = lane >> 4;          // batch within warp
    const int i    = lane & 7;           // state row
    const int c    = (lane >> 3) & 1;    // column half
    const int cb   = 4 * c;              // own column base
    const int ob   = 4 - cb;             // other column base
    const int b    = blockIdx.x * 2 + lb;

    float* wsp   = sw + lb * WSF;
    float* sPU   = wsp;          // 64: P_u, row stride 8
    float* sF    = wsp + 64;     // 96: F, row stride 12
    float* sHP   = wsp + 160;    // 16: (hp0,hp1) interleaved per column
    float* sMU   = wsp + 176;    //  8: updated mean
    float* sMean = wsp + 184;    //  8: predicted mean

    const float R00 = gR[0], R01 = gR[1], R10 = gR[2], R11 = gR[3];
    float Qr[4];
#pragma unroll
    for (int m = 0; m < 4; ++m) Qr[m] = gQ[i * 8 + cb + m];

    float* omb = oMean + (size_t)b * Tt * 8;
    float* ocb = oCov  + (size_t)b * Tt * 64;

    // ---- init: own quarter-row of P; t=0 outputs ----
    float pr[4];
    {
        const float4 p0 = *(const float4*)(gCov0 + i * 8 + cb);
        pr[0]=p0.x; pr[1]=p0.y; pr[2]=p0.z; pr[3]=p0.w;
        *(float4*)(ocb + i * 8 + cb) = p0;
    }
    if (c == 0) {
        const float m0 = gMean0[b * 8 + i];
        sMean[i] = m0;
        omb[i]   = m0;
    }

    const float* Fb = gF + (size_t)b * Tt * 64;
    const float* Hb = gH + (size_t)b * Tt * 16;
    const float* yb = gy + (size_t)b * Tt * 2;

    // ---- prefetch step 0: own quarters only ----
    float4 fh = *(const float4*)(Fb + i * 8 + cb);   // F[i][cb..cb+3]
    float4 hA = *(const float4*)(Hb + cb);           // H[0][cb..cb+3]
    float4 hC = *(const float4*)(Hb + 8 + cb);       // H[1][cb..cb+3]
    float2 yv = *(const float2*)(yb);

    __syncwarp();

    for (int t = 0; t < Tt - 1; ++t) {
        const float fr[4]  = {fh.x, fh.y, fh.z, fh.w};
        const float hao[4] = {hA.x, hA.y, hA.z, hA.w};
        const float hco[4] = {hC.x, hC.y, hC.z, hC.w};
        const float y0 = yv.x, y1 = yv.y;

        // prefetch next step
        {
            const float* Fn = Fb + (size_t)(t + 1) * 64;
            fh = *(const float4*)(Fn + i * 8 + cb);
            const float* Hn = Hb + (size_t)(t + 1) * 16;
            hA = *(const float4*)(Hn + cb);
            hC = *(const float4*)(Hn + 8 + cb);
            yv = *(const float2*)(yb + (size_t)(t + 1) * 2);
        }

        // ---- phase 1: F quarter to SMEM; HP column i via partial + shfl ----
        *(float4*)(sF + i * 12 + cb) = make_float4(fr[0], fr[1], fr[2], fr[3]);
        float hp0 = 0.f, hp1 = 0.f;
#pragma unroll
        for (int m = 0; m < 4; ++m) {      // P[s][i] = P[i][s] (symmetric)
            hp0 += hao[m] * pr[m];
            hp1 += hco[m] * pr[m];
        }
        hp0 += __shfl_xor_sync(FULL, hp0, 8);
        hp1 += __shfl_xor_sync(FULL, hp1, 8);
        if (c == 0) *(float2*)(sHP + 2 * i) = make_float2(hp0, hp1);
        __syncwarp();  // sync A: sF, sHP visible

        // ---- phase 2: Smat, gain, P_u quarter-row, mean_u ----
        // own-half HP columns (cb..cb+3)
        float HP0o[4], HP1o[4];
        {
            const float4 u0 = *(const float4*)(sHP + 2 * cb);
            const float4 u1 = *(const float4*)(sHP + 2 * cb + 4);
            HP0o[0]=u0.x; HP1o[0]=u0.y; HP0o[1]=u0.z; HP1o[1]=u0.w;
            HP0o[2]=u1.x; HP1o[2]=u1.y; HP0o[3]=u1.z; HP1o[3]=u1.w;
        }
        float s00p = 0.f, s01p = 0.f, s10p = 0.f, s11p = 0.f;
#pragma unroll
        for (int m = 0; m < 4; ++m) {
            s00p += HP0o[m] * hao[m];
            s01p += HP0o[m] * hco[m];
            s10p += HP1o[m] * hao[m];
            s11p += HP1o[m] * hco[m];
        }
        const float s00 = R00 + s00p + __shfl_xor_sync(FULL, s00p, 8);
        const float s01 = R01 + s01p + __shfl_xor_sync(FULL, s01p, 8);
        const float s10 = R10 + s10p + __shfl_xor_sync(FULL, s10p, 8);
        const float s11 = R11 + s11p + __shfl_xor_sync(FULL, s11p, 8);
        const float inv = 1.0f / (s00 * s11 - s01 * s10);
        const float w0i = inv * ( s11 * hp0 - s01 * hp1);
        const float w1i = inv * (-s10 * hp0 + s00 * hp1);

        // P_u quarter-row
        float pu[4];
#pragma unroll
        for (int m = 0; m < 4; ++m)
            pu[m] = pr[m] - w0i * HP0o[m] - w1i * HP1o[m];
        *(float4*)(sPU + i * 8 + cb) = make_float4(pu[0], pu[1], pu[2], pu[3]);

        // residual via own-half partials + shfl
        {
            const float4 mo = *(const float4*)(sMean + cb);
            float r0p = hao[0]*mo.x + hao[1]*mo.y + hao[2]*mo.z + hao[3]*mo.w;
            float r1p = hco[0]*mo.x + hco[1]*mo.y + hco[2]*mo.z + hco[3]*mo.w;
            const float r0 = y0 - (r0p + __shfl_xor_sync(FULL, r0p, 8));
            const float r1 = y1 - (r1p + __shfl_xor_sync(FULL, r1p, 8));
            if (c == 0) sMU[i] = sMean[i] + w0i * r0 + w1i * r1;
        }
        __syncwarp();  // sync B: sPU, sMU visible; all sMean reads done

        // ---- phase 3: predict ----
        // other quarter of own F row from partner lane
        float fo[4];
#pragma unroll
        for (int m = 0; m < 4; ++m)
            fo[m] = __shfl_xor_sync(FULL, fr[m], 8);

        // G[i][own cols] = sum_j F[i][j] * Pu[j][own cols]
        float g0 = 0.f, g1 = 0.f, g2 = 0.f, g3 = 0.f;
#pragma unroll
        for (int m = 0; m < 4; ++m) {   // j in own half, coeff fr[m]
            const float4 pj = *(const float4*)(sPU + (cb + m) * 8 + cb);
            g0 += fr[m] * pj.x; g1 += fr[m] * pj.y;
            g2 += fr[m] * pj.z; g3 += fr[m] * pj.w;
        }
#pragma unroll
        for (int m = 0; m < 4; ++m) {   // j in other half, coeff fo[m]
            const float4 pj = *(const float4*)(sPU + (ob + m) * 8 + cb);
            g0 += fo[m] * pj.x; g1 += fo[m] * pj.y;
            g2 += fo[m] * pj.z; g3 += fo[m] * pj.w;
        }
        // partner's G row half: rx[m] = G[i][ob+m]
        const float rx0 = __shfl_xor_sync(FULL, g0, 8);
        const float rx1 = __shfl_xor_sync(FULL, g1, 8);
        const float rx2 = __shfl_xor_sync(FULL, g2, 8);
        const float rx3 = __shfl_xor_sync(FULL, g3, 8);

        // P'[i][cb+kk] = G_row . F[k][:] + Q   (direct-offset F reads)
        float pn[4];
#pragma unroll
        for (int kk = 0; kk < 4; ++kk) {
            const int k = cb + kk;
            const float4 qo = *(const float4*)(sF + k * 12 + cb);  // F[k][own]
            const float4 qt = *(const float4*)(sF + k * 12 + ob);  // F[k][other]
            pn[kk] = Qr[kk]
                   + g0*qo.x + g1*qo.y + g2*qo.z + g3*qo.w
                   + rx0*qt.x + rx1*qt.y + rx2*qt.z + rx3*qt.w;
        }
#pragma unroll
        for (int m = 0; m < 4; ++m) pr[m] = pn[m];

        *(float4*)(ocb + (size_t)(t + 1) * 64 + i * 8 + cb) =
            make_float4(pn[0], pn[1], pn[2], pn[3]);

        // mean predict: own-half partial + shfl
        {
            const float4 muo = *(const float4*)(sMU + cb);
            float mpp = fr[0]*muo.x + fr[1]*muo.y + fr[2]*muo.z + fr[3]*muo.w;
            const float mp = mpp + __shfl_xor_sync(FULL, mpp, 8);
            if (c == 0) {
                sMean[i] = mp;   // old-sMean reads all ended before sync B
                omb[(size_t)(t + 1) * 8 + i] = mp;
            }
        }
        __syncwarp();  // sync C: phase-3 SMEM reads done; sMean visible next iter
    }
}

extern "C" void kernel_launch(void* const* d_in, const int* in_sizes, int n_in,
                              void* d_out, int out_size)
{
    // metadata order: y, F, H, Q, R, init_mean, init_cov, n_step
    const float* gy     = (const float*)d_in[0];
    const float* gF     = (const float*)d_in[1];
    const float* gH     = (const float*)d_in[2];
    const float* gQ     = (const float*)d_in[3];
    const float* gR     = (const float*)d_in[4];
    const float* gMean0 = (const float*)d_in[5];
    const float* gCov0  = (const float*)d_in[6];
    (void)in_sizes; (void)n_in;

    float* oMean = (float*)d_out;                          // [B,T,8]
    float* oCov  = (float*)d_out + (size_t)Bb * Tt * 8;    // [B,T,8,8]
    (void)out_size;

    kalman_kernel<<<Bb / 2, 32>>>(gy, gF, gH, gQ, gR, gMean0, gCov0,
                                  oMean, oCov);
}